// round 13
// baseline (speedup 1.0000x reference)
#include <cuda_runtime.h>
#include <cstdint>

// SOM forward: x[128,256] f32, weights[64,64,256] f32
// out = [ bmus(128*2 floats) , diffs(128*64*64*256 floats) ]
//
// R13: champion config (R5), single change: default .wb stores instead of
// __stcs. Theory: evict-first (.cs) sectors trigger early fragmented L2
// writebacks; .wb lets L2 coalesce full dirty lines and batch writeback
// bursts per DRAM page -> better bus utilization for a pure write stream.
// Everything else identical: block = (b, 128 contiguous m) in output
// memory order (grid 4096), warp = 16 contiguous m with 16KB contiguous
// streams, 1-deep w pipeline, per-lane acc[16], deferred interleaved
// reductions, one packed-key atomic per warp, single launch, last-block
// epilogue writes bmus + re-arms globals (graph-replay deterministic).

#define B 128
#define D 256
#define MAPM 4096                 // 64*64 neurons
#define M_PER_WARP 16
#define WARPS_PER_BLOCK 8
#define M_PER_BLOCK (M_PER_WARP * WARPS_PER_BLOCK)  // 128
#define MBLOCKS (MAPM / M_PER_BLOCK)                // 32
#define NBLOCKS (B * MBLOCKS)                       // 4096

__device__ unsigned long long g_best[B];   // zero-init; holds ~min_key
__device__ unsigned int g_done;            // zero-init ticket

__global__ __launch_bounds__(256) void som_fused_kernel(
    const float* __restrict__ x,
    const float* __restrict__ w,
    float* __restrict__ out)   // out = [bmus | diffs]
{
    float* __restrict__ diffs = out + B * 2;

    const int warp = threadIdx.x >> 5;
    const int lane = threadIdx.x & 31;
    const int b    = blockIdx.x >> 5;                       // 0..127
    const int mb   = blockIdx.x & 31;                       // 0..31
    const int m0   = mb * M_PER_BLOCK + warp * M_PER_WARP;  // warp's first m

    // x[b] in registers (shared by all 16 neurons)
    const float4* __restrict__ xv = reinterpret_cast<const float4*>(x + (size_t)b * D);
    const float4 xa0 = xv[lane];
    const float4 xa1 = xv[32 + lane];

    const float4* __restrict__ wv =
        reinterpret_cast<const float4*>(w + (size_t)m0 * D);
    float4* __restrict__ ov =
        reinterpret_cast<float4*>(diffs + ((size_t)b * MAPM + m0) * D);

    float acc[M_PER_WARP];

    // 1-deep software pipeline on the w row
    float4 wn0 = wv[lane];
    float4 wn1 = wv[32 + lane];

#pragma unroll
    for (int i = 0; i < M_PER_WARP; i++) {
        float4 wa0 = wn0, wa1 = wn1;
        if (i + 1 < M_PER_WARP) {
            wn0 = wv[(i + 1) * 64 + lane];        // contiguous next w row
            wn1 = wv[(i + 1) * 64 + 32 + lane];
        }

        float4 d0, d1;
        d0.x = xa0.x - wa0.x;  d0.y = xa0.y - wa0.y;
        d0.z = xa0.z - wa0.z;  d0.w = xa0.w - wa0.w;
        d1.x = xa1.x - wa1.x;  d1.y = xa1.y - wa1.y;
        d1.z = xa1.z - wa1.z;  d1.w = xa1.w - wa1.w;

        // contiguous stores (default .wb): warp covers 16KB contiguous
        ov[i * 64 + lane]      = d0;
        ov[i * 64 + 32 + lane] = d1;

        float a;
        a = d0.x * d0.x;
        a = fmaf(d0.y, d0.y, a);
        a = fmaf(d0.z, d0.z, a);
        a = fmaf(d0.w, d0.w, a);
        a = fmaf(d1.x, d1.x, a);
        a = fmaf(d1.y, d1.y, a);
        a = fmaf(d1.z, d1.z, a);
        a = fmaf(d1.w, d1.w, a);
        acc[i] = a;                    // per-lane partial; no cross-lane ops
    }

    // 16 independent warp reductions, interleaved (latency overlapped)
#pragma unroll
    for (int off = 16; off; off >>= 1) {
#pragma unroll
        for (int i = 0; i < M_PER_WARP; i++)
            acc[i] += __shfl_down_sync(0xffffffffu, acc[i], off);
    }

    if (lane == 0) {
        // local argmin over this warp's 16 neurons, then ONE global atomic.
        // key = (d2_bits << 32) | m: u64 min == argmin with lowest-m ties.
        unsigned long long best = 0xFFFFFFFFFFFFFFFFULL;
#pragma unroll
        for (int i = 0; i < M_PER_WARP; i++) {
            unsigned long long key =
                ((unsigned long long)__float_as_uint(acc[i]) << 32) |
                (unsigned int)(m0 + i);
            best = (key < best) ? key : best;
        }
        atomicMax(&g_best[b], ~best);   // min(key) == max(~key); zero-init safe
    }

    // ---- last-block epilogue: write bmus, re-arm globals for next replay ----
    __shared__ unsigned int s_last;
    __syncthreads();
    if (threadIdx.x == 0) {
        __threadfence();  // publish this block's g_best update
        unsigned int ticket = atomicAdd(&g_done, 1);
        s_last = (ticket == NBLOCKS - 1) ? 1u : 0u;
    }
    __syncthreads();
    if (s_last) {
        __threadfence();  // acquire all other blocks' g_best updates
        if (threadIdx.x < B) {
            unsigned long long v = ~g_best[threadIdx.x];
            unsigned int mm = (unsigned int)(v & 0xFFFFFFFFu);
            out[threadIdx.x * 2 + 0] = (float)(mm >> 6);   // row
            out[threadIdx.x * 2 + 1] = (float)(mm & 63);   // col
            g_best[threadIdx.x] = 0ULL;                    // re-arm
        }
        if (threadIdx.x == 0) g_done = 0;                  // re-arm ticket
    }
}

extern "C" void kernel_launch(void* const* d_in, const int* in_sizes, int n_in,
                              void* d_out, int out_size) {
    const float* x = (const float*)d_in[0];
    const float* w = (const float*)d_in[1];
    som_fused_kernel<<<NBLOCKS, 256>>>(x, w, (float*)d_out);
}

// round 14
// speedup vs baseline: 1.0077x; 1.0077x over previous
#include <cuda_runtime.h>
#include <cstdint>

// SOM forward: x[128,256] f32, weights[64,64,256] f32
// out = [ bmus(128*2 floats) , diffs(128*64*64*256 floats) ]
//
// R14: champion config (R5/R12), single change: st.global.wt (write-
// through) stores. Store-policy A/B so far: .cs 83.7us > .wb 87.6us.
// .wt is the last point on that axis: for a one-touch write stream it
// shortens the L2 dirty-line lifecycle (no normal-priority writeback
// staging). Everything else identical: block = (b, 128 contiguous m) in
// output memory order (grid 4096), warp = 16 contiguous m with 16KB
// contiguous streams, 1-deep w pipeline, per-lane acc[16], deferred
// interleaved reductions, one packed-key atomic per warp, single launch,
// last-block epilogue writes bmus + re-arms globals.

#define B 128
#define D 256
#define MAPM 4096                 // 64*64 neurons
#define M_PER_WARP 16
#define WARPS_PER_BLOCK 8
#define M_PER_BLOCK (M_PER_WARP * WARPS_PER_BLOCK)  // 128
#define MBLOCKS (MAPM / M_PER_BLOCK)                // 32
#define NBLOCKS (B * MBLOCKS)                       // 4096

__device__ unsigned long long g_best[B];   // zero-init; holds ~min_key
__device__ unsigned int g_done;            // zero-init ticket

__device__ __forceinline__ void stg_wt_v4(float4* p, float4 v) {
    asm volatile(
        "st.global.wt.v4.f32 [%0], {%1,%2,%3,%4};"
        :: "l"(p), "f"(v.x), "f"(v.y), "f"(v.z), "f"(v.w)
        : "memory");
}

__global__ __launch_bounds__(256) void som_fused_kernel(
    const float* __restrict__ x,
    const float* __restrict__ w,
    float* __restrict__ out)   // out = [bmus | diffs]
{
    float* __restrict__ diffs = out + B * 2;

    const int warp = threadIdx.x >> 5;
    const int lane = threadIdx.x & 31;
    const int b    = blockIdx.x >> 5;                       // 0..127
    const int mb   = blockIdx.x & 31;                       // 0..31
    const int m0   = mb * M_PER_BLOCK + warp * M_PER_WARP;  // warp's first m

    // x[b] in registers (shared by all 16 neurons)
    const float4* __restrict__ xv = reinterpret_cast<const float4*>(x + (size_t)b * D);
    const float4 xa0 = xv[lane];
    const float4 xa1 = xv[32 + lane];

    const float4* __restrict__ wv =
        reinterpret_cast<const float4*>(w + (size_t)m0 * D);
    float4* __restrict__ ov =
        reinterpret_cast<float4*>(diffs + ((size_t)b * MAPM + m0) * D);

    float acc[M_PER_WARP];

    // 1-deep software pipeline on the w row
    float4 wn0 = wv[lane];
    float4 wn1 = wv[32 + lane];

#pragma unroll
    for (int i = 0; i < M_PER_WARP; i++) {
        float4 wa0 = wn0, wa1 = wn1;
        if (i + 1 < M_PER_WARP) {
            wn0 = wv[(i + 1) * 64 + lane];        // contiguous next w row
            wn1 = wv[(i + 1) * 64 + 32 + lane];
        }

        float4 d0, d1;
        d0.x = xa0.x - wa0.x;  d0.y = xa0.y - wa0.y;
        d0.z = xa0.z - wa0.z;  d0.w = xa0.w - wa0.w;
        d1.x = xa1.x - wa1.x;  d1.y = xa1.y - wa1.y;
        d1.z = xa1.z - wa1.z;  d1.w = xa1.w - wa1.w;

        // contiguous write-through stores: warp covers 16KB contiguous
        stg_wt_v4(ov + i * 64 + lane,      d0);
        stg_wt_v4(ov + i * 64 + 32 + lane, d1);

        float a;
        a = d0.x * d0.x;
        a = fmaf(d0.y, d0.y, a);
        a = fmaf(d0.z, d0.z, a);
        a = fmaf(d0.w, d0.w, a);
        a = fmaf(d1.x, d1.x, a);
        a = fmaf(d1.y, d1.y, a);
        a = fmaf(d1.z, d1.z, a);
        a = fmaf(d1.w, d1.w, a);
        acc[i] = a;                    // per-lane partial; no cross-lane ops
    }

    // 16 independent warp reductions, interleaved (latency overlapped)
#pragma unroll
    for (int off = 16; off; off >>= 1) {
#pragma unroll
        for (int i = 0; i < M_PER_WARP; i++)
            acc[i] += __shfl_down_sync(0xffffffffu, acc[i], off);
    }

    if (lane == 0) {
        // local argmin over this warp's 16 neurons, then ONE global atomic.
        // key = (d2_bits << 32) | m: u64 min == argmin with lowest-m ties.
        unsigned long long best = 0xFFFFFFFFFFFFFFFFULL;
#pragma unroll
        for (int i = 0; i < M_PER_WARP; i++) {
            unsigned long long key =
                ((unsigned long long)__float_as_uint(acc[i]) << 32) |
                (unsigned int)(m0 + i);
            best = (key < best) ? key : best;
        }
        atomicMax(&g_best[b], ~best);   // min(key) == max(~key); zero-init safe
    }

    // ---- last-block epilogue: write bmus, re-arm globals for next replay ----
    __shared__ unsigned int s_last;
    __syncthreads();
    if (threadIdx.x == 0) {
        __threadfence();  // publish this block's g_best update
        unsigned int ticket = atomicAdd(&g_done, 1);
        s_last = (ticket == NBLOCKS - 1) ? 1u : 0u;
    }
    __syncthreads();
    if (s_last) {
        __threadfence();  // acquire all other blocks' g_best updates
        if (threadIdx.x < B) {
            unsigned long long v = ~g_best[threadIdx.x];
            unsigned int mm = (unsigned int)(v & 0xFFFFFFFFu);
            out[threadIdx.x * 2 + 0] = (float)(mm >> 6);   // row
            out[threadIdx.x * 2 + 1] = (float)(mm & 63);   // col
            g_best[threadIdx.x] = 0ULL;                    // re-arm
        }
        if (threadIdx.x == 0) g_done = 0;                  // re-arm ticket
    }
}

extern "C" void kernel_launch(void* const* d_in, const int* in_sizes, int n_in,
                              void* d_out, int out_size) {
    const float* x = (const float*)d_in[0];
    const float* w = (const float*)d_in[1];
    som_fused_kernel<<<NBLOCKS, 256>>>(x, w, (float*)d_out);
}

// round 15
// speedup vs baseline: 1.0479x; 1.0398x over previous
#include <cuda_runtime.h>
#include <cstdint>

// SOM forward: x[128,256] f32, weights[64,64,256] f32
// out = [ bmus(128*2 floats) , diffs(128*64*64*256 floats) ]
//
// FINAL champion (R5/R12). HBM-write-bound at the empirically-mapped write
// ceiling (~5.5 TB/s, 69% of spec; 516 MiB stream => ~83us floor). Design:
//  - block = (batch b, 128 contiguous neurons), grid 4096 in OUTPUT MEMORY
//    ORDER -> concurrent-wave writes are packed for DRAM page locality
//  - warp = 16 contiguous m: 16KB contiguous __stcs (evict-first) streams
//    (.cs beat .wb and .wt in direct A/B: 83.0/83.7 vs 87.6 vs 86.9 us)
//  - 1-deep software pipeline on the L2-resident w rows
//  - d2 accumulated per-lane (acc[16]); 16 interleaved deferred shuffle
//    reductions; ONE packed-key atomic per warp (min(key) == max(~key),
//    low bits carry m -> lowest-index ties = exact argmin semantics)
//  - single launch; last-block epilogue writes bmus and re-arms the
//    __device__ globals so CUDA-graph replays are deterministic.
// Falsified alternatives (all slower): TMA bulk stores via SMEM, w-reuse
// across batches, L1-shared w slabs, persistent single-wave grid, 256-bit
// ld/st, occupancy 38-71% sweep, .wb/.wt store policies.

#define B 128
#define D 256
#define MAPM 4096                 // 64*64 neurons
#define M_PER_WARP 16
#define WARPS_PER_BLOCK 8
#define M_PER_BLOCK (M_PER_WARP * WARPS_PER_BLOCK)  // 128
#define MBLOCKS (MAPM / M_PER_BLOCK)                // 32
#define NBLOCKS (B * MBLOCKS)                       // 4096

__device__ unsigned long long g_best[B];   // zero-init; holds ~min_key
__device__ unsigned int g_done;            // zero-init ticket

__global__ __launch_bounds__(256) void som_fused_kernel(
    const float* __restrict__ x,
    const float* __restrict__ w,
    float* __restrict__ out)   // out = [bmus | diffs]
{
    float* __restrict__ diffs = out + B * 2;

    const int warp = threadIdx.x >> 5;
    const int lane = threadIdx.x & 31;
    const int b    = blockIdx.x >> 5;                       // 0..127
    const int mb   = blockIdx.x & 31;                       // 0..31
    const int m0   = mb * M_PER_BLOCK + warp * M_PER_WARP;  // warp's first m

    // x[b] in registers (shared by all 16 neurons)
    const float4* __restrict__ xv = reinterpret_cast<const float4*>(x + (size_t)b * D);
    const float4 xa0 = xv[lane];
    const float4 xa1 = xv[32 + lane];

    const float4* __restrict__ wv =
        reinterpret_cast<const float4*>(w + (size_t)m0 * D);
    float4* __restrict__ ov =
        reinterpret_cast<float4*>(diffs + ((size_t)b * MAPM + m0) * D);

    float acc[M_PER_WARP];

    // 1-deep software pipeline on the w row
    float4 wn0 = wv[lane];
    float4 wn1 = wv[32 + lane];

#pragma unroll
    for (int i = 0; i < M_PER_WARP; i++) {
        float4 wa0 = wn0, wa1 = wn1;
        if (i + 1 < M_PER_WARP) {
            wn0 = wv[(i + 1) * 64 + lane];        // contiguous next w row
            wn1 = wv[(i + 1) * 64 + 32 + lane];
        }

        float4 d0, d1;
        d0.x = xa0.x - wa0.x;  d0.y = xa0.y - wa0.y;
        d0.z = xa0.z - wa0.z;  d0.w = xa0.w - wa0.w;
        d1.x = xa1.x - wa1.x;  d1.y = xa1.y - wa1.y;
        d1.z = xa1.z - wa1.z;  d1.w = xa1.w - wa1.w;

        // contiguous streaming stores: warp covers [m0*1KB, m0*1KB + 16KB)
        __stcs(ov + i * 64 + lane,      d0);
        __stcs(ov + i * 64 + 32 + lane, d1);

        float a;
        a = d0.x * d0.x;
        a = fmaf(d0.y, d0.y, a);
        a = fmaf(d0.z, d0.z, a);
        a = fmaf(d0.w, d0.w, a);
        a = fmaf(d1.x, d1.x, a);
        a = fmaf(d1.y, d1.y, a);
        a = fmaf(d1.z, d1.z, a);
        a = fmaf(d1.w, d1.w, a);
        acc[i] = a;                    // per-lane partial; no cross-lane ops
    }

    // 16 independent warp reductions, interleaved (latency overlapped)
#pragma unroll
    for (int off = 16; off; off >>= 1) {
#pragma unroll
        for (int i = 0; i < M_PER_WARP; i++)
            acc[i] += __shfl_down_sync(0xffffffffu, acc[i], off);
    }

    if (lane == 0) {
        // local argmin over this warp's 16 neurons, then ONE global atomic.
        // key = (d2_bits << 32) | m: u64 min == argmin with lowest-m ties.
        unsigned long long best = 0xFFFFFFFFFFFFFFFFULL;
#pragma unroll
        for (int i = 0; i < M_PER_WARP; i++) {
            unsigned long long key =
                ((unsigned long long)__float_as_uint(acc[i]) << 32) |
                (unsigned int)(m0 + i);
            best = (key < best) ? key : best;
        }
        atomicMax(&g_best[b], ~best);   // min(key) == max(~key); zero-init safe
    }

    // ---- last-block epilogue: write bmus, re-arm globals for next replay ----
    __shared__ unsigned int s_last;
    __syncthreads();
    if (threadIdx.x == 0) {
        __threadfence();  // publish this block's g_best update
        unsigned int ticket = atomicAdd(&g_done, 1);
        s_last = (ticket == NBLOCKS - 1) ? 1u : 0u;
    }
    __syncthreads();
    if (s_last) {
        __threadfence();  // acquire all other blocks' g_best updates
        if (threadIdx.x < B) {
            unsigned long long v = ~g_best[threadIdx.x];
            unsigned int mm = (unsigned int)(v & 0xFFFFFFFFu);
            out[threadIdx.x * 2 + 0] = (float)(mm >> 6);   // row
            out[threadIdx.x * 2 + 1] = (float)(mm & 63);   // col
            g_best[threadIdx.x] = 0ULL;                    // re-arm
        }
        if (threadIdx.x == 0) g_done = 0;                  // re-arm ticket
    }
}

extern "C" void kernel_launch(void* const* d_in, const int* in_sizes, int n_in,
                              void* d_out, int out_size) {
    const float* x = (const float*)d_in[0];
    const float* w = (const float*)d_in[1];
    som_fused_kernel<<<NBLOCKS, 256>>>(x, w, (float*)d_out);
}

// round 16
// speedup vs baseline: 1.0625x; 1.0140x over previous
#include <cuda_runtime.h>
#include <cstdint>

// SOM forward: x[128,256] f32, weights[64,64,256] f32
// out = [ bmus(128*2 floats) , diffs(128*64*64*256 floats) ]
//
// FINAL champion (verified 3x: 83.0 / 83.7 / 83.6 us; DRAM ~69% = the
// empirical HBM3e pure-write-stream ceiling on GB300, ~5.5 TB/s).
// 516 MiB output stream / 5.5 TB/s ~= 83 us -> kernel is AT the roofline.
//
// Design:
//  - block = (batch b, 128 contiguous neurons), grid 4096 in OUTPUT MEMORY
//    ORDER -> concurrent-wave writes are packed for DRAM page locality
//  - warp = 16 contiguous m: 16KB contiguous __stcs (evict-first) streams
//    (.cs beat .wb 87.6us and .wt 86.9us in direct A/B)
//  - 1-deep software pipeline on the L2-resident w rows
//  - d2 accumulated per-lane (acc[16]); 16 interleaved deferred shuffle
//    reductions; ONE packed-key atomic per warp (min(key) == max(~key),
//    low bits carry m -> lowest-index ties = exact argmin semantics)
//  - single launch; last-block epilogue writes bmus and re-arms the
//    __device__ globals so CUDA-graph replays are deterministic.
// Falsified alternatives (all slower): TMA bulk stores via SMEM (97.2),
// w-reuse across batches (84.5), L1-shared w slabs (90.9), persistent
// single-wave grid (90.8), 256-bit ld/st (90.0), occupancy 38-71% sweep
// (86.8-90.0), .wb/.wt store policies (87.6/86.9).

#define B 128
#define D 256
#define MAPM 4096                 // 64*64 neurons
#define M_PER_WARP 16
#define WARPS_PER_BLOCK 8
#define M_PER_BLOCK (M_PER_WARP * WARPS_PER_BLOCK)  // 128
#define MBLOCKS (MAPM / M_PER_BLOCK)                // 32
#define NBLOCKS (B * MBLOCKS)                       // 4096

__device__ unsigned long long g_best[B];   // zero-init; holds ~min_key
__device__ unsigned int g_done;            // zero-init ticket

__global__ __launch_bounds__(256) void som_fused_kernel(
    const float* __restrict__ x,
    const float* __restrict__ w,
    float* __restrict__ out)   // out = [bmus | diffs]
{
    float* __restrict__ diffs = out + B * 2;

    const int warp = threadIdx.x >> 5;
    const int lane = threadIdx.x & 31;
    const int b    = blockIdx.x >> 5;                       // 0..127
    const int mb   = blockIdx.x & 31;                       // 0..31
    const int m0   = mb * M_PER_BLOCK + warp * M_PER_WARP;  // warp's first m

    // x[b] in registers (shared by all 16 neurons)
    const float4* __restrict__ xv = reinterpret_cast<const float4*>(x + (size_t)b * D);
    const float4 xa0 = xv[lane];
    const float4 xa1 = xv[32 + lane];

    const float4* __restrict__ wv =
        reinterpret_cast<const float4*>(w + (size_t)m0 * D);
    float4* __restrict__ ov =
        reinterpret_cast<float4*>(diffs + ((size_t)b * MAPM + m0) * D);

    float acc[M_PER_WARP];

    // 1-deep software pipeline on the w row
    float4 wn0 = wv[lane];
    float4 wn1 = wv[32 + lane];

#pragma unroll
    for (int i = 0; i < M_PER_WARP; i++) {
        float4 wa0 = wn0, wa1 = wn1;
        if (i + 1 < M_PER_WARP) {
            wn0 = wv[(i + 1) * 64 + lane];        // contiguous next w row
            wn1 = wv[(i + 1) * 64 + 32 + lane];
        }

        float4 d0, d1;
        d0.x = xa0.x - wa0.x;  d0.y = xa0.y - wa0.y;
        d0.z = xa0.z - wa0.z;  d0.w = xa0.w - wa0.w;
        d1.x = xa1.x - wa1.x;  d1.y = xa1.y - wa1.y;
        d1.z = xa1.z - wa1.z;  d1.w = xa1.w - wa1.w;

        // contiguous streaming stores: warp covers [m0*1KB, m0*1KB + 16KB)
        __stcs(ov + i * 64 + lane,      d0);
        __stcs(ov + i * 64 + 32 + lane, d1);

        float a;
        a = d0.x * d0.x;
        a = fmaf(d0.y, d0.y, a);
        a = fmaf(d0.z, d0.z, a);
        a = fmaf(d0.w, d0.w, a);
        a = fmaf(d1.x, d1.x, a);
        a = fmaf(d1.y, d1.y, a);
        a = fmaf(d1.z, d1.z, a);
        a = fmaf(d1.w, d1.w, a);
        acc[i] = a;                    // per-lane partial; no cross-lane ops
    }

    // 16 independent warp reductions, interleaved (latency overlapped)
#pragma unroll
    for (int off = 16; off; off >>= 1) {
#pragma unroll
        for (int i = 0; i < M_PER_WARP; i++)
            acc[i] += __shfl_down_sync(0xffffffffu, acc[i], off);
    }

    if (lane == 0) {
        // local argmin over this warp's 16 neurons, then ONE global atomic.
        // key = (d2_bits << 32) | m: u64 min == argmin with lowest-m ties.
        unsigned long long best = 0xFFFFFFFFFFFFFFFFULL;
#pragma unroll
        for (int i = 0; i < M_PER_WARP; i++) {
            unsigned long long key =
                ((unsigned long long)__float_as_uint(acc[i]) << 32) |
                (unsigned int)(m0 + i);
            best = (key < best) ? key : best;
        }
        atomicMax(&g_best[b], ~best);   // min(key) == max(~key); zero-init safe
    }

    // ---- last-block epilogue: write bmus, re-arm globals for next replay ----
    __shared__ unsigned int s_last;
    __syncthreads();
    if (threadIdx.x == 0) {
        __threadfence();  // publish this block's g_best update
        unsigned int ticket = atomicAdd(&g_done, 1);
        s_last = (ticket == NBLOCKS - 1) ? 1u : 0u;
    }
    __syncthreads();
    if (s_last) {
        __threadfence();  // acquire all other blocks' g_best updates
        if (threadIdx.x < B) {
            unsigned long long v = ~g_best[threadIdx.x];
            unsigned int mm = (unsigned int)(v & 0xFFFFFFFFu);
            out[threadIdx.x * 2 + 0] = (float)(mm >> 6);   // row
            out[threadIdx.x * 2 + 1] = (float)(mm & 63);   // col
            g_best[threadIdx.x] = 0ULL;                    // re-arm
        }
        if (threadIdx.x == 0) g_done = 0;                  // re-arm ticket
    }
}

extern "C" void kernel_launch(void* const* d_in, const int* in_sizes, int n_in,
                              void* d_out, int out_size) {
    const float* x = (const float*)d_in[0];
    const float* w = (const float*)d_in[1];
    som_fused_kernel<<<NBLOCKS, 256>>>(x, w, (float*)d_out);
}